// round 10
// baseline (speedup 1.0000x reference)
#include <cuda_runtime.h>
#include <cstdint>

#define NN 100000
#define NE 1600000
#define DC 128
#define NL 3
#define NBLK 98          // ceil(NN/1024)
#define NCHUNK 4
#define CHUNK_ROWS 25088 // 196 tiles of 128; last chunk is remainder

// ---------------- scratch (device globals; no allocations allowed) ----------
__device__ float g_z [(size_t)NN * DC];
__device__ float g_t1[(size_t)NN * DC];
__device__ float g_t2[(size_t)NN * DC];
__device__ float g_stats[2 * DC];
__device__ float g_aff [2 * DC];
__device__ int   g_deg[NN];
__device__ int   g_pos[NN];
__device__ int   g_off[NN + 1];
__device__ int   g_csr[NE];
__device__ int   g_bsum[NBLK];

// ---------------- side stream + events (created at static init, pre-checkpoint)
struct SideStream {
    cudaStream_t s2;
    cudaEvent_t  evF, evJ;
    SideStream() {
        cudaStreamCreateWithFlags(&s2, cudaStreamNonBlocking);
        cudaEventCreateWithFlags(&evF, cudaEventDisableTiming);
        cudaEventCreateWithFlags(&evJ, cudaEventDisableTiming);
    }
};
static SideStream g_ss;

// ---------------- tiny utility kernels --------------------------------------
__global__ void k_zero_stats() { g_stats[threadIdx.x] = 0.f; }

__global__ void k_zero_deg()
{
    int i = blockIdx.x * blockDim.x + threadIdx.x;
    if (i < NN) g_deg[i] = 0;
}

// final output: out = a*in + c (BN2 of last layer, no ReLU)
__global__ void k_affine(const float* __restrict__ in, float* __restrict__ out)
{
    int i = blockIdx.x * blockDim.x + threadIdx.x;
    const int n4 = NN * DC / 4;
    if (i >= n4) return;
    float4 v = __ldg((const float4*)in + i);
    int c4 = i & (DC / 4 - 1);
    float4 a = *((const float4*)g_aff + c4);
    float4 c = *((const float4*)g_aff + DC / 4 + c4);
    v.x = fmaf(a.x, v.x, c.x);
    v.y = fmaf(a.y, v.y, c.y);
    v.z = fmaf(a.z, v.z, c.z);
    v.w = fmaf(a.w, v.w, c.w);
    ((float4*)out)[i] = v;
}

// ---------------- CSR build ---------------------------------------------------
__global__ void k_hist(const int* __restrict__ ei)
{
    int q = blockIdx.x * blockDim.x + threadIdx.x;
    if (q >= NE / 4) return;
    int4 d = __ldg((const int4*)(ei + NE) + q);
    atomicAdd(&g_deg[d.x], 1);
    atomicAdd(&g_deg[d.y], 1);
    atomicAdd(&g_deg[d.z], 1);
    atomicAdd(&g_deg[d.w], 1);
}

__global__ void k_scan1()
{
    __shared__ int ws[32];
    int t = threadIdx.x;
    int i = blockIdx.x * 1024 + t;
    int v = (i < NN) ? g_deg[i] : 0;
    #pragma unroll
    for (int d = 16; d; d >>= 1) v += __shfl_down_sync(0xFFFFFFFF, v, d);
    if ((t & 31) == 0) ws[t >> 5] = v;
    __syncthreads();
    if (t < 32) {
        int x = ws[t];
        #pragma unroll
        for (int d = 16; d; d >>= 1) x += __shfl_down_sync(0xFFFFFFFF, x, d);
        if (t == 0) g_bsum[blockIdx.x] = x;
    }
}

__global__ void k_scan2()
{
    __shared__ int s[128];
    int t = threadIdx.x;
    s[t] = (t < NBLK) ? g_bsum[t] : 0;
    __syncthreads();
    for (int off = 1; off < 128; off <<= 1) {
        int v = s[t];
        int a = (t >= off) ? s[t - off] : 0;
        __syncthreads();
        s[t] = v + a;
        __syncthreads();
    }
    if (t < NBLK) g_bsum[t] = (t > 0) ? s[t - 1] : 0;
}

__global__ void k_scan3()
{
    __shared__ int ws[32];
    int t = threadIdx.x;
    int lane = t & 31, wid = t >> 5;
    int i = blockIdx.x * 1024 + t;
    int v = (i < NN) ? g_deg[i] : 0;
    int incl = v;
    #pragma unroll
    for (int d = 1; d < 32; d <<= 1) {
        int n = __shfl_up_sync(0xFFFFFFFF, incl, d);
        if (lane >= d) incl += n;
    }
    if (lane == 31) ws[wid] = incl;
    __syncthreads();
    if (wid == 0) {
        int x = ws[lane];
        #pragma unroll
        for (int d = 1; d < 32; d <<= 1) {
            int n = __shfl_up_sync(0xFFFFFFFF, x, d);
            if (lane >= d) x += n;
        }
        ws[lane] = x;
    }
    __syncthreads();
    int excl = incl - v + ((wid > 0) ? ws[wid - 1] : 0) + g_bsum[blockIdx.x];
    if (i < NN) { g_off[i] = excl; g_pos[i] = excl; }
    if (i == 0) g_off[NN] = NE;
}

__global__ void k_fill(const int* __restrict__ ei)
{
    int q = blockIdx.x * blockDim.x + threadIdx.x;
    if (q >= NE / 4) return;
    int4 s = __ldg((const int4*)ei + q);
    int4 d = __ldg((const int4*)(ei + NE) + q);
    g_csr[atomicAdd(&g_pos[d.x], 1)] = s.x;
    g_csr[atomicAdd(&g_pos[d.y], 1)] = s.y;
    g_csr[atomicAdd(&g_pos[d.z], 1)] = s.z;
    g_csr[atomicAdd(&g_pos[d.w], 1)] = s.w;
}

// ---------------- CSR aggregation over node range [node0, node1) -------------
// warp per node; 2 edges/iter, row loads pipelined 1 iteration deep.
template<bool AFF>
__global__ void k_aggr(const float* __restrict__ h, int relu, int node0, int node1)
{
    int gt = blockIdx.x * blockDim.x + threadIdx.x;
    int n = node0 + (gt >> 5);
    int lane = gt & 31;
    if (n >= node1) return;

    float4 a, c;
    if (AFF) {
        a = *((const float4*)g_aff + lane);
        c = *((const float4*)g_aff + DC / 4 + lane);
    }

    auto raw = [&](int s) -> float4 {
        return __ldg((const float4*)(h + (size_t)s * DC) + lane);
    };
    auto post = [&](float4 v) -> float4 {
        if (AFF) {
            v.x = fmaf(a.x, v.x, c.x);
            v.y = fmaf(a.y, v.y, c.y);
            v.z = fmaf(a.z, v.z, c.z);
            v.w = fmaf(a.w, v.w, c.w);
            if (relu) {
                v.x = fmaxf(v.x, 0.f); v.y = fmaxf(v.y, 0.f);
                v.z = fmaxf(v.z, 0.f); v.w = fmaxf(v.w, 0.f);
            }
        }
        return v;
    };

    const int i0 = __ldg(g_off + n);
    const int i1 = __ldg(g_off + n + 1);
    const int len = i1 - i0;

    float4 acc0 = post(raw(n));   // self term (eps = 0)
    float4 acc1 = make_float4(0.f, 0.f, 0.f, 0.f);

    if (len == 1) {
        float4 v = post(raw(__ldg(g_csr + i0)));
        acc0.x += v.x; acc0.y += v.y; acc0.z += v.z; acc0.w += v.w;
    } else if (len >= 2) {
        float4 v0 = raw(__ldg(g_csr + i0));
        float4 v1 = raw(__ldg(g_csr + i0 + 1));
        int i = i0 + 2;
        for (; i + 1 < i1; i += 2) {
            float4 va = raw(__ldg(g_csr + i));
            float4 vb = raw(__ldg(g_csr + i + 1));
            float4 p0 = post(v0), p1 = post(v1);
            acc0.x += p0.x; acc0.y += p0.y; acc0.z += p0.z; acc0.w += p0.w;
            acc1.x += p1.x; acc1.y += p1.y; acc1.z += p1.z; acc1.w += p1.w;
            v0 = va; v1 = vb;
        }
        float4 p0 = post(v0), p1 = post(v1);
        acc0.x += p0.x; acc0.y += p0.y; acc0.z += p0.z; acc0.w += p0.w;
        acc1.x += p1.x; acc1.y += p1.y; acc1.z += p1.z; acc1.w += p1.w;
        if (i < i1) {
            float4 v = post(raw(__ldg(g_csr + i)));
            acc0.x += v.x; acc0.y += v.y; acc0.z += v.z; acc0.w += v.w;
        }
    }
    acc0.x += acc1.x; acc0.y += acc1.y; acc0.z += acc1.z; acc0.w += acc1.w;
    *((float4*)(g_z + (size_t)n * DC) + lane) = acc0;
}

// ---------------- fp32 FFMA GEMM + bias + BN-stats, 2 CTAs/SM ----------------
// out[m][n] = sum_k f(A[m][k]) * W[k][n] + bias[n]; K chunked 2x64.
// row0: row offset of this launch's first tile (for chunked overlap launches).
#define KCH 64
#define SAP 68   // A pitch (floats)

template<bool AFF>
__global__ void __launch_bounds__(256, 2)
k_gemm(const float* __restrict__ A, const float* __restrict__ W,
       const float* __restrict__ bias, float* __restrict__ out, int nrows, int row0)
{
    extern __shared__ float sm[];
    float* sA   = sm;                    // [128][SAP]  (chunk-local k)
    float* sB   = sm + 128 * SAP;        // [KCH][128]
    float* sSum = sB + KCH * 128;        // [128]
    float* sSq  = sSum + DC;             // [128]

    const int t = threadIdx.x;
    const int blockRow = row0 + blockIdx.x * 128;

    if (t < DC) { sSum[t] = 0.f; sSq[t] = 0.f; }

    const int tx = t & 15, ty = t >> 4;
    const int m0 = ty * 8, n0 = tx * 8;

    float acc[8][8];
    #pragma unroll
    for (int i = 0; i < 8; i++)
        #pragma unroll
        for (int j = 0; j < 8; j++)
            acc[i][j] = 0.f;

    for (int kc = 0; kc < 2; kc++) {
        #pragma unroll
        for (int i = 0; i < 8; i++) {
            int idx = i * 256 + t;          // float4 idx over 64x128
            int kl  = idx >> 5;
            int n4  = idx & 31;
            float4 v = __ldg((const float4*)W + (kc * KCH + kl) * 32 + n4);
            *(float4*)(sB + kl * 128 + n4 * 4) = v;
        }
        #pragma unroll
        for (int i = 0; i < 8; i++) {
            int idx = i * 256 + t;          // float4 idx over 128x64
            int m   = idx >> 4;
            int k4  = idx & 15;
            int gm  = blockRow + m;
            float4 v = make_float4(0.f, 0.f, 0.f, 0.f);
            if (gm < nrows) {
                v = __ldg((const float4*)(A + (size_t)gm * DC) + kc * 16 + k4);
                if (AFF) {
                    float4 a = *((const float4*)g_aff + kc * 16 + k4);
                    float4 c = *((const float4*)g_aff + DC / 4 + kc * 16 + k4);
                    v.x = fmaxf(fmaf(a.x, v.x, c.x), 0.f);
                    v.y = fmaxf(fmaf(a.y, v.y, c.y), 0.f);
                    v.z = fmaxf(fmaf(a.z, v.z, c.z), 0.f);
                    v.w = fmaxf(fmaf(a.w, v.w, c.w), 0.f);
                }
            }
            *(float4*)(sA + m * SAP + k4 * 4) = v;
        }
        __syncthreads();

        #pragma unroll 2
        for (int k0 = 0; k0 < KCH; k0 += 4) {
            float4 av[8];
            #pragma unroll
            for (int i = 0; i < 8; i++)
                av[i] = *(const float4*)(sA + (m0 + i) * SAP + k0);
            #pragma unroll
            for (int kk = 0; kk < 4; kk++) {
                float4 b0 = *(const float4*)(sB + (k0 + kk) * 128 + n0);
                float4 b1 = *(const float4*)(sB + (k0 + kk) * 128 + n0 + 4);
                #pragma unroll
                for (int i = 0; i < 8; i++) {
                    float a = (kk == 0) ? av[i].x : (kk == 1) ? av[i].y
                            : (kk == 2) ? av[i].z : av[i].w;
                    acc[i][0] = fmaf(a, b0.x, acc[i][0]);
                    acc[i][1] = fmaf(a, b0.y, acc[i][1]);
                    acc[i][2] = fmaf(a, b0.z, acc[i][2]);
                    acc[i][3] = fmaf(a, b0.w, acc[i][3]);
                    acc[i][4] = fmaf(a, b1.x, acc[i][4]);
                    acc[i][5] = fmaf(a, b1.y, acc[i][5]);
                    acc[i][6] = fmaf(a, b1.z, acc[i][6]);
                    acc[i][7] = fmaf(a, b1.w, acc[i][7]);
                }
            }
        }
        __syncthreads();
    }

    // ---- epilogue: bias, store, per-channel stats ----
    float4 bv0 = __ldg((const float4*)(bias + n0));
    float4 bv1 = __ldg((const float4*)(bias + n0) + 1);
    float csum[8] = {0, 0, 0, 0, 0, 0, 0, 0};
    float csq [8] = {0, 0, 0, 0, 0, 0, 0, 0};
    #pragma unroll
    for (int i = 0; i < 8; i++) {
        int gm = blockRow + m0 + i;
        float v0 = acc[i][0] + bv0.x, v1 = acc[i][1] + bv0.y;
        float v2 = acc[i][2] + bv0.z, v3 = acc[i][3] + bv0.w;
        float v4 = acc[i][4] + bv1.x, v5 = acc[i][5] + bv1.y;
        float v6 = acc[i][6] + bv1.z, v7 = acc[i][7] + bv1.w;
        if (gm < nrows) {
            float* po = out + (size_t)gm * DC + n0;
            *(float4*)po       = make_float4(v0, v1, v2, v3);
            *(float4*)(po + 4) = make_float4(v4, v5, v6, v7);
            csum[0] += v0; csq[0] += v0 * v0;
            csum[1] += v1; csq[1] += v1 * v1;
            csum[2] += v2; csq[2] += v2 * v2;
            csum[3] += v3; csq[3] += v3 * v3;
            csum[4] += v4; csq[4] += v4 * v4;
            csum[5] += v5; csq[5] += v5 * v5;
            csum[6] += v6; csq[6] += v6 * v6;
            csum[7] += v7; csq[7] += v7 * v7;
        }
    }
    #pragma unroll
    for (int j = 0; j < 8; j++) {
        atomicAdd(&sSum[n0 + j], csum[j]);
        atomicAdd(&sSq [n0 + j], csq [j]);
    }
    __syncthreads();
    if (t < DC) {
        atomicAdd(&g_stats[t],      sSum[t]);
        atomicAdd(&g_stats[DC + t], sSq[t]);
    }
}

// ---------------- BN stats -> affine; reset stats ----------------------------
__global__ void k_bn(const float* __restrict__ gamma, const float* __restrict__ beta)
{
    int c = threadIdx.x;
    float s  = g_stats[c];
    float sq = g_stats[DC + c];
    const float inv_n = 1.f / (float)NN;
    float mu  = s * inv_n;
    float var = fmaxf(sq * inv_n - mu * mu, 0.f);
    float a = __ldg(gamma + c) * rsqrtf(var + 1e-5f);
    g_aff[c]      = a;
    g_aff[DC + c] = __ldg(beta + c) - mu * a;
    g_stats[c]      = 0.f;
    g_stats[DC + c] = 0.f;
}

// ---------------- launcher ----------------------------------------------------
extern "C" void kernel_launch(void* const* d_in, const int* in_sizes, int n_in,
                              void* d_out, int out_size)
{
    const float* x   = (const float*)d_in[0];
    const int*   ei  = (const int*)  d_in[1];
    const float* W1  = (const float*)d_in[4];
    const float* b1  = (const float*)d_in[5];
    const float* g1  = (const float*)d_in[6];
    const float* be1 = (const float*)d_in[7];
    const float* W2  = (const float*)d_in[8];
    const float* b2  = (const float*)d_in[9];
    const float* g2  = (const float*)d_in[10];
    const float* be2 = (const float*)d_in[11];
    float* out = (float*)d_out;

    float *zp, *t1p, *t2p;
    cudaGetSymbolAddress((void**)&zp,  g_z);
    cudaGetSymbolAddress((void**)&t1p, g_t1);
    cudaGetSymbolAddress((void**)&t2p, g_t2);

    const size_t SMEM = (size_t)(128 * SAP + KCH * 128 + 2 * DC) * sizeof(float);
    cudaFuncSetAttribute(k_gemm<false>, cudaFuncAttributeMaxDynamicSharedMemorySize, (int)SMEM);
    cudaFuncSetAttribute(k_gemm<true>,  cudaFuncAttributeMaxDynamicSharedMemorySize, (int)SMEM);

    const int AFF_BLOCKS  = (NN * DC / 4 + 255) / 256;
    const int E4_BLOCKS   = (NE / 4 + 255) / 256;
    const int N_BLOCKS    = (NN + 255) / 256;
    const int GEMM_BLOCKS = (NN + 127) / 128;

    // CSR build (every launch; deterministic)
    k_zero_stats<<<1, 256>>>();
    k_zero_deg<<<N_BLOCKS, 256>>>();
    k_hist<<<E4_BLOCKS, 256>>>(ei);
    k_scan1<<<NBLK, 1024>>>();
    k_scan2<<<1, 128>>>();
    k_scan3<<<NBLK, 1024>>>();
    k_fill<<<E4_BLOCKS, 256>>>(ei);

    const float* h = x;
    for (int l = 0; l < NL; l++) {
        // --- overlapped: aggr chunk c (stream 0)  ∥  GEMM1 chunk c-1 (s2) ---
        for (int c = 0; c < NCHUNK; c++) {
            const int n0 = c * CHUNK_ROWS;
            const int n1 = (c == NCHUNK - 1) ? NN : n0 + CHUNK_ROWS;
            const int aggrBlk = ((n1 - n0) * 32 + 255) / 256;
            const int tiles   = (n1 - n0 + 127) / 128;
            if (l == 0)
                k_aggr<false><<<aggrBlk, 256>>>(h, 0, n0, n1);
            else
                k_aggr<true><<<aggrBlk, 256>>>(h, 1, n0, n1);   // prev BN2+ReLU fused
            cudaEventRecord(g_ss.evF, 0);
            cudaStreamWaitEvent(g_ss.s2, g_ss.evF, 0);
            k_gemm<false><<<tiles, 256, SMEM, g_ss.s2>>>(
                zp, W1 + l * DC * DC, b1 + l * DC, t1p, NN, n0);
        }
        cudaEventRecord(g_ss.evJ, g_ss.s2);
        cudaStreamWaitEvent(0, g_ss.evJ, 0);

        k_bn<<<1, DC>>>(g1 + l * DC, be1 + l * DC);
        // GEMM2: BN1+ReLU fused on A load -> t2 + stats
        k_gemm<true><<<GEMM_BLOCKS, 256, SMEM>>>(t1p, W2 + l * DC * DC, b2 + l * DC, t2p, NN, 0);
        k_bn<<<1, DC>>>(g2 + l * DC, be2 + l * DC);
        h = t2p;
    }
    k_affine<<<AFF_BLOCKS, 256>>>(t2p, out);   // final BN2, no ReLU
}

// round 11
// speedup vs baseline: 1.0387x; 1.0387x over previous
#include <cuda_runtime.h>
#include <cstdint>

#define NN 100000
#define NE 1600000
#define DC 128
#define NL 3
#define NBLK 98          // ceil(NN/1024)

// ---------------- scratch (device globals; no allocations allowed) ----------
__device__ float g_z [(size_t)NN * DC];
__device__ float g_t1[(size_t)NN * DC];
__device__ float g_t2[(size_t)NN * DC];
__device__ float g_stats[2 * DC];
__device__ float g_aff [2 * DC];
__device__ int   g_deg[NN];
__device__ int   g_pos[NN];
__device__ int   g_off[NN + 1];
__device__ int   g_csr[NE];
__device__ int   g_bsum[NBLK];

// ---------------- packed fp32x2 helpers --------------------------------------
__device__ __forceinline__ uint64_t pack2(float lo, float hi)
{
    uint64_t r;
    asm("mov.b64 %0, {%1, %2};" : "=l"(r) : "f"(lo), "f"(hi));
    return r;
}
__device__ __forceinline__ void unpack2(uint64_t v, float& lo, float& hi)
{
    asm("mov.b64 {%0, %1}, %2;" : "=f"(lo), "=f"(hi) : "l"(v));
}
__device__ __forceinline__ void fma2(uint64_t& acc, uint64_t a, uint64_t b)
{
    asm("fma.rn.f32x2 %0, %1, %2, %0;" : "+l"(acc) : "l"(a), "l"(b));
}

// ---------------- tiny utility kernels --------------------------------------
__global__ void k_zero_stats() { g_stats[threadIdx.x] = 0.f; }

__global__ void k_zero_deg()
{
    int i = blockIdx.x * blockDim.x + threadIdx.x;
    if (i < NN) g_deg[i] = 0;
}

// final output: out = a*in + c (BN2 of last layer, no ReLU)
__global__ void k_affine(const float* __restrict__ in, float* __restrict__ out)
{
    int i = blockIdx.x * blockDim.x + threadIdx.x;
    const int n4 = NN * DC / 4;
    if (i >= n4) return;
    float4 v = __ldg((const float4*)in + i);
    int c4 = i & (DC / 4 - 1);
    float4 a = *((const float4*)g_aff + c4);
    float4 c = *((const float4*)g_aff + DC / 4 + c4);
    v.x = fmaf(a.x, v.x, c.x);
    v.y = fmaf(a.y, v.y, c.y);
    v.z = fmaf(a.z, v.z, c.z);
    v.w = fmaf(a.w, v.w, c.w);
    ((float4*)out)[i] = v;
}

// ---------------- CSR build ---------------------------------------------------
__global__ void k_hist(const int* __restrict__ ei)
{
    int q = blockIdx.x * blockDim.x + threadIdx.x;
    if (q >= NE / 4) return;
    int4 d = __ldg((const int4*)(ei + NE) + q);
    atomicAdd(&g_deg[d.x], 1);
    atomicAdd(&g_deg[d.y], 1);
    atomicAdd(&g_deg[d.z], 1);
    atomicAdd(&g_deg[d.w], 1);
}

__global__ void k_scan1()
{
    __shared__ int ws[32];
    int t = threadIdx.x;
    int i = blockIdx.x * 1024 + t;
    int v = (i < NN) ? g_deg[i] : 0;
    #pragma unroll
    for (int d = 16; d; d >>= 1) v += __shfl_down_sync(0xFFFFFFFF, v, d);
    if ((t & 31) == 0) ws[t >> 5] = v;
    __syncthreads();
    if (t < 32) {
        int x = ws[t];
        #pragma unroll
        for (int d = 16; d; d >>= 1) x += __shfl_down_sync(0xFFFFFFFF, x, d);
        if (t == 0) g_bsum[blockIdx.x] = x;
    }
}

__global__ void k_scan2()
{
    __shared__ int s[128];
    int t = threadIdx.x;
    s[t] = (t < NBLK) ? g_bsum[t] : 0;
    __syncthreads();
    for (int off = 1; off < 128; off <<= 1) {
        int v = s[t];
        int a = (t >= off) ? s[t - off] : 0;
        __syncthreads();
        s[t] = v + a;
        __syncthreads();
    }
    if (t < NBLK) g_bsum[t] = (t > 0) ? s[t - 1] : 0;
}

__global__ void k_scan3()
{
    __shared__ int ws[32];
    int t = threadIdx.x;
    int lane = t & 31, wid = t >> 5;
    int i = blockIdx.x * 1024 + t;
    int v = (i < NN) ? g_deg[i] : 0;
    int incl = v;
    #pragma unroll
    for (int d = 1; d < 32; d <<= 1) {
        int n = __shfl_up_sync(0xFFFFFFFF, incl, d);
        if (lane >= d) incl += n;
    }
    if (lane == 31) ws[wid] = incl;
    __syncthreads();
    if (wid == 0) {
        int x = ws[lane];
        #pragma unroll
        for (int d = 1; d < 32; d <<= 1) {
            int n = __shfl_up_sync(0xFFFFFFFF, x, d);
            if (lane >= d) x += n;
        }
        ws[lane] = x;
    }
    __syncthreads();
    int excl = incl - v + ((wid > 0) ? ws[wid - 1] : 0) + g_bsum[blockIdx.x];
    if (i < NN) { g_off[i] = excl; g_pos[i] = excl; }
    if (i == 0) g_off[NN] = NE;
}

__global__ void k_fill(const int* __restrict__ ei)
{
    int q = blockIdx.x * blockDim.x + threadIdx.x;
    if (q >= NE / 4) return;
    int4 s = __ldg((const int4*)ei + q);
    int4 d = __ldg((const int4*)(ei + NE) + q);
    g_csr[atomicAdd(&g_pos[d.x], 1)] = s.x;
    g_csr[atomicAdd(&g_pos[d.y], 1)] = s.y;
    g_csr[atomicAdd(&g_pos[d.z], 1)] = s.z;
    g_csr[atomicAdd(&g_pos[d.w], 1)] = s.w;
}

// ---------------- CSR aggregation: z[n] = f(h[n]) + sum_{s in N(n)} f(h[s]) ---
// warp per node; 2 edges/iter, row loads pipelined 1 iteration deep.
template<bool AFF>
__global__ void k_aggr(const float* __restrict__ h, int relu)
{
    int gt = blockIdx.x * blockDim.x + threadIdx.x;
    int n = gt >> 5;
    int lane = gt & 31;
    if (n >= NN) return;

    float4 a, c;
    if (AFF) {
        a = *((const float4*)g_aff + lane);
        c = *((const float4*)g_aff + DC / 4 + lane);
    }

    auto raw = [&](int s) -> float4 {
        return __ldg((const float4*)(h + (size_t)s * DC) + lane);
    };
    auto post = [&](float4 v) -> float4 {
        if (AFF) {
            v.x = fmaf(a.x, v.x, c.x);
            v.y = fmaf(a.y, v.y, c.y);
            v.z = fmaf(a.z, v.z, c.z);
            v.w = fmaf(a.w, v.w, c.w);
            if (relu) {
                v.x = fmaxf(v.x, 0.f); v.y = fmaxf(v.y, 0.f);
                v.z = fmaxf(v.z, 0.f); v.w = fmaxf(v.w, 0.f);
            }
        }
        return v;
    };

    const int i0 = __ldg(g_off + n);
    const int i1 = __ldg(g_off + n + 1);
    const int len = i1 - i0;

    float4 acc0 = post(raw(n));   // self term (eps = 0)
    float4 acc1 = make_float4(0.f, 0.f, 0.f, 0.f);

    if (len == 1) {
        float4 v = post(raw(__ldg(g_csr + i0)));
        acc0.x += v.x; acc0.y += v.y; acc0.z += v.z; acc0.w += v.w;
    } else if (len >= 2) {
        float4 v0 = raw(__ldg(g_csr + i0));
        float4 v1 = raw(__ldg(g_csr + i0 + 1));
        int i = i0 + 2;
        for (; i + 1 < i1; i += 2) {
            float4 va = raw(__ldg(g_csr + i));
            float4 vb = raw(__ldg(g_csr + i + 1));
            float4 p0 = post(v0), p1 = post(v1);
            acc0.x += p0.x; acc0.y += p0.y; acc0.z += p0.z; acc0.w += p0.w;
            acc1.x += p1.x; acc1.y += p1.y; acc1.z += p1.z; acc1.w += p1.w;
            v0 = va; v1 = vb;
        }
        float4 p0 = post(v0), p1 = post(v1);
        acc0.x += p0.x; acc0.y += p0.y; acc0.z += p0.z; acc0.w += p0.w;
        acc1.x += p1.x; acc1.y += p1.y; acc1.z += p1.z; acc1.w += p1.w;
        if (i < i1) {
            float4 v = post(raw(__ldg(g_csr + i)));
            acc0.x += v.x; acc0.y += v.y; acc0.z += v.z; acc0.w += v.w;
        }
    }
    acc0.x += acc1.x; acc0.y += acc1.y; acc0.z += acc1.z; acc0.w += acc1.w;
    *((float4*)(g_z + (size_t)n * DC) + lane) = acc0;
}

// ---------------- packed-fp32x2 FFMA2 GEMM + bias + BN-stats, 2 CTAs/SM ------
// out[m][n] = sum_k f(A[m][k]) * W[k][n] + bias[n]; K chunked 2x64.
// Per-thread tile: 8 m-rows x 4 packed n-pairs. B pairs load directly as b64
// from smem (n contiguous); A broadcast-packed (a,a) once per m per k.
#define KCH 64
#define SAP 68   // A pitch (floats)

template<bool AFF>
__global__ void __launch_bounds__(256, 2)
k_gemm(const float* __restrict__ A, const float* __restrict__ W,
       const float* __restrict__ bias, float* __restrict__ out, int nrows)
{
    extern __shared__ float sm[];
    float* sA   = sm;                    // [128][SAP]  (chunk-local k)
    float* sB   = sm + 128 * SAP;        // [KCH][128]
    float* sSum = sB + KCH * 128;        // [128]
    float* sSq  = sSum + DC;             // [128]

    const int t = threadIdx.x;
    const int blockRow = blockIdx.x * 128;

    if (t < DC) { sSum[t] = 0.f; sSq[t] = 0.f; }

    const int tx = t & 15, ty = t >> 4;
    const int m0 = ty * 8, n0 = tx * 8;

    uint64_t acc[8][4];                  // 8 m-rows x 4 n-pairs (f32x2)
    #pragma unroll
    for (int i = 0; i < 8; i++)
        #pragma unroll
        for (int j = 0; j < 4; j++)
            acc[i][j] = 0ull;

    for (int kc = 0; kc < 2; kc++) {
        #pragma unroll
        for (int i = 0; i < 8; i++) {
            int idx = i * 256 + t;          // float4 idx over 64x128
            int kl  = idx >> 5;
            int n4  = idx & 31;
            float4 v = __ldg((const float4*)W + (kc * KCH + kl) * 32 + n4);
            *(float4*)(sB + kl * 128 + n4 * 4) = v;
        }
        #pragma unroll
        for (int i = 0; i < 8; i++) {
            int idx = i * 256 + t;          // float4 idx over 128x64
            int m   = idx >> 4;
            int k4  = idx & 15;
            int gm  = blockRow + m;
            float4 v = make_float4(0.f, 0.f, 0.f, 0.f);
            if (gm < nrows) {
                v = __ldg((const float4*)(A + (size_t)gm * DC) + kc * 16 + k4);
                if (AFF) {
                    float4 a = *((const float4*)g_aff + kc * 16 + k4);
                    float4 c = *((const float4*)g_aff + DC / 4 + kc * 16 + k4);
                    v.x = fmaxf(fmaf(a.x, v.x, c.x), 0.f);
                    v.y = fmaxf(fmaf(a.y, v.y, c.y), 0.f);
                    v.z = fmaxf(fmaf(a.z, v.z, c.z), 0.f);
                    v.w = fmaxf(fmaf(a.w, v.w, c.w), 0.f);
                }
            }
            *(float4*)(sA + m * SAP + k4 * 4) = v;
        }
        __syncthreads();

        #pragma unroll 2
        for (int k0 = 0; k0 < KCH; k0 += 4) {
            float4 av[8];
            #pragma unroll
            for (int i = 0; i < 8; i++)
                av[i] = *(const float4*)(sA + (m0 + i) * SAP + k0);
            #pragma unroll
            for (int kk = 0; kk < 4; kk++) {
                float4 bq0 = *(const float4*)(sB + (k0 + kk) * 128 + n0);
                float4 bq1 = *(const float4*)(sB + (k0 + kk) * 128 + n0 + 4);
                uint64_t b0 = pack2(bq0.x, bq0.y);
                uint64_t b1 = pack2(bq0.z, bq0.w);
                uint64_t b2 = pack2(bq1.x, bq1.y);
                uint64_t b3 = pack2(bq1.z, bq1.w);
                #pragma unroll
                for (int i = 0; i < 8; i++) {
                    float a = (kk == 0) ? av[i].x : (kk == 1) ? av[i].y
                            : (kk == 2) ? av[i].z : av[i].w;
                    uint64_t ap = pack2(a, a);
                    fma2(acc[i][0], ap, b0);
                    fma2(acc[i][1], ap, b1);
                    fma2(acc[i][2], ap, b2);
                    fma2(acc[i][3], ap, b3);
                }
            }
        }
        __syncthreads();
    }

    // ---- epilogue: bias, store, per-channel stats ----
    float4 bv0 = __ldg((const float4*)(bias + n0));
    float4 bv1 = __ldg((const float4*)(bias + n0) + 1);
    float csum[8] = {0, 0, 0, 0, 0, 0, 0, 0};
    float csq [8] = {0, 0, 0, 0, 0, 0, 0, 0};
    #pragma unroll
    for (int i = 0; i < 8; i++) {
        int gm = blockRow + m0 + i;
        float v0, v1, v2, v3, v4, v5, v6, v7;
        unpack2(acc[i][0], v0, v1);
        unpack2(acc[i][1], v2, v3);
        unpack2(acc[i][2], v4, v5);
        unpack2(acc[i][3], v6, v7);
        v0 += bv0.x; v1 += bv0.y; v2 += bv0.z; v3 += bv0.w;
        v4 += bv1.x; v5 += bv1.y; v6 += bv1.z; v7 += bv1.w;
        if (gm < nrows) {
            float* po = out + (size_t)gm * DC + n0;
            *(float4*)po       = make_float4(v0, v1, v2, v3);
            *(float4*)(po + 4) = make_float4(v4, v5, v6, v7);
            csum[0] += v0; csq[0] += v0 * v0;
            csum[1] += v1; csq[1] += v1 * v1;
            csum[2] += v2; csq[2] += v2 * v2;
            csum[3] += v3; csq[3] += v3 * v3;
            csum[4] += v4; csq[4] += v4 * v4;
            csum[5] += v5; csq[5] += v5 * v5;
            csum[6] += v6; csq[6] += v6 * v6;
            csum[7] += v7; csq[7] += v7 * v7;
        }
    }
    #pragma unroll
    for (int j = 0; j < 8; j++) {
        atomicAdd(&sSum[n0 + j], csum[j]);
        atomicAdd(&sSq [n0 + j], csq [j]);
    }
    __syncthreads();
    if (t < DC) {
        atomicAdd(&g_stats[t],      sSum[t]);
        atomicAdd(&g_stats[DC + t], sSq[t]);
    }
}

// ---------------- BN stats -> affine; reset stats ----------------------------
__global__ void k_bn(const float* __restrict__ gamma, const float* __restrict__ beta)
{
    int c = threadIdx.x;
    float s  = g_stats[c];
    float sq = g_stats[DC + c];
    const float inv_n = 1.f / (float)NN;
    float mu  = s * inv_n;
    float var = fmaxf(sq * inv_n - mu * mu, 0.f);
    float a = __ldg(gamma + c) * rsqrtf(var + 1e-5f);
    g_aff[c]      = a;
    g_aff[DC + c] = __ldg(beta + c) - mu * a;
    g_stats[c]      = 0.f;
    g_stats[DC + c] = 0.f;
}

// ---------------- launcher ----------------------------------------------------
extern "C" void kernel_launch(void* const* d_in, const int* in_sizes, int n_in,
                              void* d_out, int out_size)
{
    const float* x   = (const float*)d_in[0];
    const int*   ei  = (const int*)  d_in[1];
    const float* W1  = (const float*)d_in[4];
    const float* b1  = (const float*)d_in[5];
    const float* g1  = (const float*)d_in[6];
    const float* be1 = (const float*)d_in[7];
    const float* W2  = (const float*)d_in[8];
    const float* b2  = (const float*)d_in[9];
    const float* g2  = (const float*)d_in[10];
    const float* be2 = (const float*)d_in[11];
    float* out = (float*)d_out;

    float *zp, *t1p, *t2p;
    cudaGetSymbolAddress((void**)&zp,  g_z);
    cudaGetSymbolAddress((void**)&t1p, g_t1);
    cudaGetSymbolAddress((void**)&t2p, g_t2);

    const size_t SMEM = (size_t)(128 * SAP + KCH * 128 + 2 * DC) * sizeof(float);
    cudaFuncSetAttribute(k_gemm<false>, cudaFuncAttributeMaxDynamicSharedMemorySize, (int)SMEM);
    cudaFuncSetAttribute(k_gemm<true>,  cudaFuncAttributeMaxDynamicSharedMemorySize, (int)SMEM);

    const int AFF_BLOCKS  = (NN * DC / 4 + 255) / 256;
    const int E4_BLOCKS   = (NE / 4 + 255) / 256;
    const int N_BLOCKS    = (NN + 255) / 256;
    const int AGG_BLOCKS  = (NN * 32 + 255) / 256;
    const int GEMM_BLOCKS = (NN + 127) / 128;

    // CSR build (every launch; deterministic)
    k_zero_stats<<<1, 256>>>();
    k_zero_deg<<<N_BLOCKS, 256>>>();
    k_hist<<<E4_BLOCKS, 256>>>(ei);
    k_scan1<<<NBLK, 1024>>>();
    k_scan2<<<1, 128>>>();
    k_scan3<<<NBLK, 1024>>>();
    k_fill<<<E4_BLOCKS, 256>>>(ei);

    const float* h = x;
    for (int l = 0; l < NL; l++) {
        if (l == 0)
            k_aggr<false><<<AGG_BLOCKS, 256>>>(h, 0);
        else
            k_aggr<true><<<AGG_BLOCKS, 256>>>(h, 1);   // prev BN2+ReLU fused
        k_gemm<false><<<GEMM_BLOCKS, 256, SMEM>>>(zp, W1 + l * DC * DC, b1 + l * DC, t1p, NN);
        k_bn<<<1, DC>>>(g1 + l * DC, be1 + l * DC);
        k_gemm<true><<<GEMM_BLOCKS, 256, SMEM>>>(t1p, W2 + l * DC * DC, b2 + l * DC, t2p, NN);
        k_bn<<<1, DC>>>(g2 + l * DC, be2 + l * DC);
        h = t2p;
    }
    k_affine<<<AFF_BLOCKS, 256>>>(t2p, out);   // final BN2, no ReLU
}

// round 12
// speedup vs baseline: 1.0588x; 1.0194x over previous
#include <cuda_runtime.h>
#include <cstdint>

#define NN 100000
#define NE 1600000
#define DC 128
#define NL 3
#define NBLK 98          // ceil(NN/1024)

// ---------------- scratch (device globals; no allocations allowed) ----------
// g_stats invariant: zero at entry of every kernel_launch. Zero-initialized at
// module load; k_bn re-zeroes each slot immediately after consuming it.
__device__ float g_z [(size_t)NN * DC];
__device__ float g_t1[(size_t)NN * DC];
__device__ float g_t2[(size_t)NN * DC];
__device__ float g_stats[2 * DC];
__device__ float g_aff [2 * DC];
__device__ int   g_deg[NN];
__device__ int   g_pos[NN];
__device__ int   g_off[NN + 1];
__device__ int   g_csr[NE];
__device__ int   g_bsum[NBLK];

// ---------------- tiny utility kernels --------------------------------------
__global__ void k_zero_deg()
{
    int i = blockIdx.x * blockDim.x + threadIdx.x;
    if (i < NN) g_deg[i] = 0;
}

// final output: out = a*in + c (BN2 of last layer, no ReLU)
__global__ void k_affine(const float* __restrict__ in, float* __restrict__ out)
{
    int i = blockIdx.x * blockDim.x + threadIdx.x;
    const int n4 = NN * DC / 4;
    if (i >= n4) return;
    float4 v = __ldg((const float4*)in + i);
    int c4 = i & (DC / 4 - 1);
    float4 a = *((const float4*)g_aff + c4);
    float4 c = *((const float4*)g_aff + DC / 4 + c4);
    v.x = fmaf(a.x, v.x, c.x);
    v.y = fmaf(a.y, v.y, c.y);
    v.z = fmaf(a.z, v.z, c.z);
    v.w = fmaf(a.w, v.w, c.w);
    ((float4*)out)[i] = v;
}

// ---------------- CSR build ---------------------------------------------------
__global__ void k_hist(const int* __restrict__ ei)
{
    int q = blockIdx.x * blockDim.x + threadIdx.x;
    if (q >= NE / 4) return;
    int4 d = __ldg((const int4*)(ei + NE) + q);
    atomicAdd(&g_deg[d.x], 1);
    atomicAdd(&g_deg[d.y], 1);
    atomicAdd(&g_deg[d.z], 1);
    atomicAdd(&g_deg[d.w], 1);
}

__global__ void k_scan1()
{
    __shared__ int ws[32];
    int t = threadIdx.x;
    int i = blockIdx.x * 1024 + t;
    int v = (i < NN) ? g_deg[i] : 0;
    #pragma unroll
    for (int d = 16; d; d >>= 1) v += __shfl_down_sync(0xFFFFFFFF, v, d);
    if ((t & 31) == 0) ws[t >> 5] = v;
    __syncthreads();
    if (t < 32) {
        int x = ws[t];
        #pragma unroll
        for (int d = 16; d; d >>= 1) x += __shfl_down_sync(0xFFFFFFFF, x, d);
        if (t == 0) g_bsum[blockIdx.x] = x;
    }
}

__global__ void k_scan2()
{
    __shared__ int s[128];
    int t = threadIdx.x;
    s[t] = (t < NBLK) ? g_bsum[t] : 0;
    __syncthreads();
    for (int off = 1; off < 128; off <<= 1) {
        int v = s[t];
        int a = (t >= off) ? s[t - off] : 0;
        __syncthreads();
        s[t] = v + a;
        __syncthreads();
    }
    if (t < NBLK) g_bsum[t] = (t > 0) ? s[t - 1] : 0;
}

__global__ void k_scan3()
{
    __shared__ int ws[32];
    int t = threadIdx.x;
    int lane = t & 31, wid = t >> 5;
    int i = blockIdx.x * 1024 + t;
    int v = (i < NN) ? g_deg[i] : 0;
    int incl = v;
    #pragma unroll
    for (int d = 1; d < 32; d <<= 1) {
        int n = __shfl_up_sync(0xFFFFFFFF, incl, d);
        if (lane >= d) incl += n;
    }
    if (lane == 31) ws[wid] = incl;
    __syncthreads();
    if (wid == 0) {
        int x = ws[lane];
        #pragma unroll
        for (int d = 1; d < 32; d <<= 1) {
            int n = __shfl_up_sync(0xFFFFFFFF, x, d);
            if (lane >= d) x += n;
        }
        ws[lane] = x;
    }
    __syncthreads();
    int excl = incl - v + ((wid > 0) ? ws[wid - 1] : 0) + g_bsum[blockIdx.x];
    if (i < NN) { g_off[i] = excl; g_pos[i] = excl; }
    if (i == 0) g_off[NN] = NE;
}

__global__ void k_fill(const int* __restrict__ ei)
{
    int q = blockIdx.x * blockDim.x + threadIdx.x;
    if (q >= NE / 4) return;
    int4 s = __ldg((const int4*)ei + q);
    int4 d = __ldg((const int4*)(ei + NE) + q);
    g_csr[atomicAdd(&g_pos[d.x], 1)] = s.x;
    g_csr[atomicAdd(&g_pos[d.y], 1)] = s.y;
    g_csr[atomicAdd(&g_pos[d.z], 1)] = s.z;
    g_csr[atomicAdd(&g_pos[d.w], 1)] = s.w;
}

// ---------------- CSR aggregation: z[n] = f(h[n]) + sum_{s in N(n)} f(h[s]) ---
// warp per node, lane covers 4 channels; BN affine(+relu) fused into reads.
template<bool AFF>
__global__ void k_aggr(const float* __restrict__ h, int relu)
{
    int gt = blockIdx.x * blockDim.x + threadIdx.x;
    int n = gt >> 5;
    int lane = gt & 31;
    if (n >= NN) return;

    float4 a, c;
    if (AFF) {
        a = *((const float4*)g_aff + lane);
        c = *((const float4*)g_aff + DC / 4 + lane);
    }

    auto fetch = [&](int s) -> float4 {
        float4 v = __ldg((const float4*)(h + (size_t)s * DC) + lane);
        if (AFF) {
            v.x = fmaf(a.x, v.x, c.x);
            v.y = fmaf(a.y, v.y, c.y);
            v.z = fmaf(a.z, v.z, c.z);
            v.w = fmaf(a.w, v.w, c.w);
            if (relu) {
                v.x = fmaxf(v.x, 0.f); v.y = fmaxf(v.y, 0.f);
                v.z = fmaxf(v.z, 0.f); v.w = fmaxf(v.w, 0.f);
            }
        }
        return v;
    };

    float4 acc = fetch(n);   // self term (eps = 0)

    const int i0 = __ldg(g_off + n);
    const int i1 = __ldg(g_off + n + 1);
    int s_cur = 0, s_nxt = 0;
    if (i0 < i1)     s_cur = __ldg(g_csr + i0);
    if (i0 + 1 < i1) s_nxt = __ldg(g_csr + i0 + 1);
    for (int i = i0; i < i1; i++) {
        int s = s_cur;
        s_cur = s_nxt;
        if (i + 2 < i1) s_nxt = __ldg(g_csr + i + 2);
        float4 v = fetch(s);
        acc.x += v.x; acc.y += v.y; acc.z += v.z; acc.w += v.w;
    }
    *((float4*)(g_z + (size_t)n * DC) + lane) = acc;
}

// ---------------- fp32 FFMA GEMM + bias + BN-stats, 2 CTAs/SM ----------------
// out[m][n] = sum_k f(A[m][k]) * W[k][n] + bias[n]; K chunked 2x64.
// 256 thr, 128x128 tile, 8x8 thread tile. Measured at the FFMA roofline.
#define KCH 64
#define SAP 68   // A pitch (floats)

template<bool AFF>
__global__ void __launch_bounds__(256, 2)
k_gemm(const float* __restrict__ A, const float* __restrict__ W,
       const float* __restrict__ bias, float* __restrict__ out, int nrows)
{
    extern __shared__ float sm[];
    float* sA   = sm;                    // [128][SAP]  (chunk-local k)
    float* sB   = sm + 128 * SAP;        // [KCH][128]
    float* sSum = sB + KCH * 128;        // [128]
    float* sSq  = sSum + DC;             // [128]

    const int t = threadIdx.x;
    const int blockRow = blockIdx.x * 128;

    if (t < DC) { sSum[t] = 0.f; sSq[t] = 0.f; }

    const int tx = t & 15, ty = t >> 4;
    const int m0 = ty * 8, n0 = tx * 8;

    float acc[8][8];
    #pragma unroll
    for (int i = 0; i < 8; i++)
        #pragma unroll
        for (int j = 0; j < 8; j++)
            acc[i][j] = 0.f;

    for (int kc = 0; kc < 2; kc++) {
        // W chunk: rows [kc*64, kc*64+64), all 128 cols
        #pragma unroll
        for (int i = 0; i < 8; i++) {
            int idx = i * 256 + t;          // float4 idx over 64x128
            int kl  = idx >> 5;
            int n4  = idx & 31;
            float4 v = __ldg((const float4*)W + (kc * KCH + kl) * 32 + n4);
            *(float4*)(sB + kl * 128 + n4 * 4) = v;
        }
        // A chunk: 128 rows x 64 cols, fused affine+relu; zero-pad invalid rows
        #pragma unroll
        for (int i = 0; i < 8; i++) {
            int idx = i * 256 + t;          // float4 idx over 128x64
            int m   = idx >> 4;
            int k4  = idx & 15;
            int gm  = blockRow + m;
            float4 v = make_float4(0.f, 0.f, 0.f, 0.f);
            if (gm < nrows) {
                v = __ldg((const float4*)(A + (size_t)gm * DC) + kc * 16 + k4);
                if (AFF) {
                    float4 a = *((const float4*)g_aff + kc * 16 + k4);
                    float4 c = *((const float4*)g_aff + DC / 4 + kc * 16 + k4);
                    v.x = fmaxf(fmaf(a.x, v.x, c.x), 0.f);
                    v.y = fmaxf(fmaf(a.y, v.y, c.y), 0.f);
                    v.z = fmaxf(fmaf(a.z, v.z, c.z), 0.f);
                    v.w = fmaxf(fmaf(a.w, v.w, c.w), 0.f);
                }
            }
            *(float4*)(sA + m * SAP + k4 * 4) = v;
        }
        __syncthreads();

        #pragma unroll 2
        for (int k0 = 0; k0 < KCH; k0 += 4) {
            float4 av[8];
            #pragma unroll
            for (int i = 0; i < 8; i++)
                av[i] = *(const float4*)(sA + (m0 + i) * SAP + k0);
            #pragma unroll
            for (int kk = 0; kk < 4; kk++) {
                float4 b0 = *(const float4*)(sB + (k0 + kk) * 128 + n0);
                float4 b1 = *(const float4*)(sB + (k0 + kk) * 128 + n0 + 4);
                #pragma unroll
                for (int i = 0; i < 8; i++) {
                    float a = (kk == 0) ? av[i].x : (kk == 1) ? av[i].y
                            : (kk == 2) ? av[i].z : av[i].w;
                    acc[i][0] = fmaf(a, b0.x, acc[i][0]);
                    acc[i][1] = fmaf(a, b0.y, acc[i][1]);
                    acc[i][2] = fmaf(a, b0.z, acc[i][2]);
                    acc[i][3] = fmaf(a, b0.w, acc[i][3]);
                    acc[i][4] = fmaf(a, b1.x, acc[i][4]);
                    acc[i][5] = fmaf(a, b1.y, acc[i][5]);
                    acc[i][6] = fmaf(a, b1.z, acc[i][6]);
                    acc[i][7] = fmaf(a, b1.w, acc[i][7]);
                }
            }
        }
        __syncthreads();
    }

    // ---- epilogue: bias, store, per-channel stats ----
    float4 bv0 = __ldg((const float4*)(bias + n0));
    float4 bv1 = __ldg((const float4*)(bias + n0) + 1);
    float csum[8] = {0, 0, 0, 0, 0, 0, 0, 0};
    float csq [8] = {0, 0, 0, 0, 0, 0, 0, 0};
    #pragma unroll
    for (int i = 0; i < 8; i++) {
        int gm = blockRow + m0 + i;
        float v0 = acc[i][0] + bv0.x, v1 = acc[i][1] + bv0.y;
        float v2 = acc[i][2] + bv0.z, v3 = acc[i][3] + bv0.w;
        float v4 = acc[i][4] + bv1.x, v5 = acc[i][5] + bv1.y;
        float v6 = acc[i][6] + bv1.z, v7 = acc[i][7] + bv1.w;
        if (gm < nrows) {
            float* po = out + (size_t)gm * DC + n0;
            *(float4*)po       = make_float4(v0, v1, v2, v3);
            *(float4*)(po + 4) = make_float4(v4, v5, v6, v7);
            csum[0] += v0; csq[0] += v0 * v0;
            csum[1] += v1; csq[1] += v1 * v1;
            csum[2] += v2; csq[2] += v2 * v2;
            csum[3] += v3; csq[3] += v3 * v3;
            csum[4] += v4; csq[4] += v4 * v4;
            csum[5] += v5; csq[5] += v5 * v5;
            csum[6] += v6; csq[6] += v6 * v6;
            csum[7] += v7; csq[7] += v7 * v7;
        }
    }
    #pragma unroll
    for (int j = 0; j < 8; j++) {
        atomicAdd(&sSum[n0 + j], csum[j]);
        atomicAdd(&sSq [n0 + j], csq [j]);
    }
    __syncthreads();
    if (t < DC) {
        atomicAdd(&g_stats[t],      sSum[t]);
        atomicAdd(&g_stats[DC + t], sSq[t]);
    }
}

// ---------------- BN stats -> affine; reset stats ----------------------------
__global__ void k_bn(const float* __restrict__ gamma, const float* __restrict__ beta)
{
    int c = threadIdx.x;
    float s  = g_stats[c];
    float sq = g_stats[DC + c];
    const float inv_n = 1.f / (float)NN;
    float mu  = s * inv_n;
    float var = fmaxf(sq * inv_n - mu * mu, 0.f);
    float a = __ldg(gamma + c) * rsqrtf(var + 1e-5f);
    g_aff[c]      = a;
    g_aff[DC + c] = __ldg(beta + c) - mu * a;
    g_stats[c]      = 0.f;   // restore the zero invariant for next GEMM/replay
    g_stats[DC + c] = 0.f;
}

// ---------------- launcher ----------------------------------------------------
extern "C" void kernel_launch(void* const* d_in, const int* in_sizes, int n_in,
                              void* d_out, int out_size)
{
    const float* x   = (const float*)d_in[0];
    const int*   ei  = (const int*)  d_in[1];
    const float* W1  = (const float*)d_in[4];
    const float* b1  = (const float*)d_in[5];
    const float* g1  = (const float*)d_in[6];
    const float* be1 = (const float*)d_in[7];
    const float* W2  = (const float*)d_in[8];
    const float* b2  = (const float*)d_in[9];
    const float* g2  = (const float*)d_in[10];
    const float* be2 = (const float*)d_in[11];
    float* out = (float*)d_out;

    float *zp, *t1p, *t2p;
    cudaGetSymbolAddress((void**)&zp,  g_z);
    cudaGetSymbolAddress((void**)&t1p, g_t1);
    cudaGetSymbolAddress((void**)&t2p, g_t2);

    const size_t SMEM = (size_t)(128 * SAP + KCH * 128 + 2 * DC) * sizeof(float);
    cudaFuncSetAttribute(k_gemm<false>, cudaFuncAttributeMaxDynamicSharedMemorySize, (int)SMEM);
    cudaFuncSetAttribute(k_gemm<true>,  cudaFuncAttributeMaxDynamicSharedMemorySize, (int)SMEM);

    const int AFF_BLOCKS  = (NN * DC / 4 + 255) / 256;
    const int E4_BLOCKS   = (NE / 4 + 255) / 256;
    const int N_BLOCKS    = (NN + 255) / 256;
    const int AGG_BLOCKS  = (NN * 32 + 255) / 256;
    const int GEMM_BLOCKS = (NN + 127) / 128;

    // CSR build (every launch; deterministic)
    k_zero_deg<<<N_BLOCKS, 256>>>();
    k_hist<<<E4_BLOCKS, 256>>>(ei);
    k_scan1<<<NBLK, 1024>>>();
    k_scan2<<<1, 128>>>();
    k_scan3<<<NBLK, 1024>>>();
    k_fill<<<E4_BLOCKS, 256>>>(ei);

    const float* h = x;
    for (int l = 0; l < NL; l++) {
        if (l == 0)
            k_aggr<false><<<AGG_BLOCKS, 256>>>(h, 0);
        else
            k_aggr<true><<<AGG_BLOCKS, 256>>>(h, 1);   // prev BN2+ReLU fused
        k_gemm<false><<<GEMM_BLOCKS, 256, SMEM>>>(zp, W1 + l * DC * DC, b1 + l * DC, t1p, NN);
        k_bn<<<1, DC>>>(g1 + l * DC, be1 + l * DC);
        k_gemm<true><<<GEMM_BLOCKS, 256, SMEM>>>(t1p, W2 + l * DC * DC, b2 + l * DC, t2p, NN);
        k_bn<<<1, DC>>>(g2 + l * DC, be2 + l * DC);
        h = t2p;
    }
    k_affine<<<AFF_BLOCKS, 256>>>(t2p, out);   // final BN2, no ReLU
}